// round 2
// baseline (speedup 1.0000x reference)
#include <cuda_runtime.h>

#define BATCH 32
#define CI    128
#define CO    256
#define HH    56
#define WW    56

#define ICB     4      // input channels per smem stage
#define TH      8      // output tile height
#define TW      8      // output tile width
#define OCT     128    // output channels per block
#define THREADS 128

// Effective kernel, k-major layout: g_weff[(ic*9 + r*3 + s)*CO + oc]
__device__ float g_weff[CI * 9 * CO];

// w_eff[o,i,r,s] = krow[o,i,s] + kcol[o,i,r]
//   krow[o,i,j] = sum_s weight[o,i,j,s]
//   kcol[o,i,j] = sum_r weight[o,i,r,j]
__global__ void build_weff_kernel(const float* __restrict__ w) {
    int idx = blockIdx.x * blockDim.x + threadIdx.x;
    if (idx >= CO * CI) return;
    int o = idx / CI;
    int i = idx % CI;
    const float* wp = w + (size_t)(o * CI + i) * 9;
    float v[9];
#pragma unroll
    for (int t = 0; t < 9; ++t) v[t] = wp[t];
    float krow[3], kcol[3];
#pragma unroll
    for (int j = 0; j < 3; ++j) {
        krow[j] = v[j * 3 + 0] + v[j * 3 + 1] + v[j * 3 + 2];
        kcol[j] = v[0 + j] + v[3 + j] + v[6 + j];
    }
#pragma unroll
    for (int r = 0; r < 3; ++r)
#pragma unroll
        for (int s = 0; s < 3; ++s)
            g_weff[(i * 9 + r * 3 + s) * CO + o] = krow[s] + kcol[r];
}

__global__ __launch_bounds__(THREADS)
void conv_kernel(const float* __restrict__ x,
                 const float* __restrict__ bias,
                 float* __restrict__ y) {
    __shared__ float sw[ICB * 9][OCT];          // 36 x 128 floats = 18 KB
    __shared__ float sx[ICB][TH + 2][12];       // rows padded to 12 floats (16B-aligned rows)

    const int tid  = threadIdx.x;
    const int tile = blockIdx.x;                // 0..48 (7x7 spatial tiles)
    const int ty   = tile / 7;
    const int tx   = tile % 7;
    const int gh0  = ty * TH;
    const int gw0  = tx * TW;
    const int ocBase = blockIdx.y * OCT;
    const int b    = blockIdx.z;

    const int prow = tid & 7;                   // pixel row within tile (0..7)
    const int ocg  = tid >> 3;                  // oc sub-block (0..15), 8 oc each

    float acc[8][8];                            // [pixel col][oc]
#pragma unroll
    for (int p = 0; p < 8; ++p)
#pragma unroll
        for (int o = 0; o < 8; ++o) acc[p][o] = 0.f;

    const float* xb = x + (size_t)b * CI * HH * WW;

    for (int kc = 0; kc < CI / ICB; ++kc) {
        __syncthreads();

        // --- stage weights: 36 k-slices x 128 oc, coalesced float4 loads ---
#pragma unroll
        for (int i = tid; i < 36 * 32; i += THREADS) {
            int k  = i >> 5;
            int o4 = i & 31;
            float4 v = *(const float4*)(g_weff + (size_t)(kc * 36 + k) * CO + ocBase + o4 * 4);
            *(float4*)&sw[k][o4 * 4] = v;
        }

        // --- stage x patch: ICB channels x 10 rows x 10 cols (+pad), zero-fill halo ---
        for (int i = tid; i < ICB * (TH + 2) * 12; i += THREADS) {
            int icl = i / 120;
            int rem = i % 120;
            int row = rem / 12;
            int col = rem % 12;
            float v = 0.f;
            int gh = gh0 + row - 1;
            int gw = gw0 + col - 1;
            if (col < 10 && gh >= 0 && gh < HH && gw >= 0 && gw < WW)
                v = xb[(size_t)(kc * ICB + icl) * HH * WW + gh * WW + gw];
            sx[icl][row][col] = v;
        }
        __syncthreads();

        // --- accumulate ---
#pragma unroll 1
        for (int icl = 0; icl < ICB; ++icl) {
#pragma unroll
            for (int r = 0; r < 3; ++r) {
                float xr[10];
#pragma unroll
                for (int j = 0; j < 10; ++j) xr[j] = sx[icl][prow + r][j];
#pragma unroll
                for (int s = 0; s < 3; ++s) {
                    const float4 w0 = *(const float4*)&sw[icl * 9 + r * 3 + s][ocg * 8];
                    const float4 w1 = *(const float4*)&sw[icl * 9 + r * 3 + s][ocg * 8 + 4];
                    const float wv[8] = {w0.x, w0.y, w0.z, w0.w, w1.x, w1.y, w1.z, w1.w};
#pragma unroll
                    for (int p = 0; p < 8; ++p) {
                        const float xv = xr[p + s];
#pragma unroll
                        for (int o = 0; o < 8; ++o)
                            acc[p][o] += xv * wv[o];
                    }
                }
            }
        }
    }

    // --- epilogue: add bias, vectorized stores (gw0 multiple of 8 -> 16B aligned) ---
#pragma unroll
    for (int o = 0; o < 8; ++o) {
        const int oc = ocBase + ocg * 8 + o;
        const float bv = bias[oc];
        float* yp = y + ((size_t)(b * CO + oc) * HH + (gh0 + prow)) * WW + gw0;
        float4 v0 = make_float4(acc[0][o] + bv, acc[1][o] + bv, acc[2][o] + bv, acc[3][o] + bv);
        float4 v1 = make_float4(acc[4][o] + bv, acc[5][o] + bv, acc[6][o] + bv, acc[7][o] + bv);
        *(float4*)yp       = v0;
        *(float4*)(yp + 4) = v1;
    }
}

extern "C" void kernel_launch(void* const* d_in, const int* in_sizes, int n_in,
                              void* d_out, int out_size) {
    const float* x    = (const float*)d_in[0];
    const float* w    = (const float*)d_in[1];
    const float* bias = (const float*)d_in[2];
    float* y = (float*)d_out;

    build_weff_kernel<<<(CO * CI + 255) / 256, 256>>>(w);

    dim3 grid(49, CO / OCT, BATCH);
    conv_kernel<<<grid, THREADS>>>(x, bias, y);
}

// round 6
// speedup vs baseline: 2.7094x; 2.7094x over previous
#include <cuda_runtime.h>
#include <cstdint>

#define BATCH 32
#define CI    128
#define CO    256
#define HH    56
#define WW    56
#define HP    58
#define WP    58
#define KTOT  1152          // CI * 9
#define NCHUNKS 36          // KTOT / 32
#define HW    (HH * WW)     // 3136

#define S_STRIDE 136        // floats per k-row in smem (136 % 32 == 8 -> conflict-free)
#define A_FLOATS (32 * S_STRIDE)          // 4352 floats per buffer
#define OFF_A0   0
#define OFF_A1   A_FLOATS
#define OFF_B0   (2 * A_FLOATS)
#define OFF_B1   (3 * A_FLOATS)
#define OFF_BIAS (4 * A_FLOATS)
#define SMEM_TOTAL ((4 * A_FLOATS + 128) * 4)

__device__ float g_xpad[BATCH * HP * WP * CI];   // NHWC, zero halo, tf32-rounded
__device__ float g_weff[CO * KTOT];              // [oc][tap*128+ic], tf32-rounded

__device__ __forceinline__ float tf32r(float v) {
    uint32_t r;
    asm("cvt.rna.tf32.f32 %0, %1;" : "=r"(r) : "f"(v));
    return __uint_as_float(r);
}

__device__ __forceinline__ void mma_tf32(float* d, const uint32_t* a, const uint32_t* b) {
    asm volatile(
        "mma.sync.aligned.m16n8k8.row.col.f32.tf32.tf32.f32 "
        "{%0,%1,%2,%3}, {%4,%5,%6,%7}, {%8,%9}, {%0,%1,%2,%3};"
        : "+f"(d[0]), "+f"(d[1]), "+f"(d[2]), "+f"(d[3])
        : "r"(a[0]), "r"(a[1]), "r"(a[2]), "r"(a[3]), "r"(b[0]), "r"(b[1]));
}

// ---------------------------------------------------------------------------
// Prep kernels
// ---------------------------------------------------------------------------
__global__ void zero_xpad_kernel() {
    const int n4 = BATCH * HP * WP * CI / 4;
    float4 z = make_float4(0.f, 0.f, 0.f, 0.f);
    for (int i = blockIdx.x * blockDim.x + threadIdx.x; i < n4; i += gridDim.x * blockDim.x)
        ((float4*)g_xpad)[i] = z;
}

// NCHW -> padded NHWC with tf32 rounding. grid = (h=56, icb=4, b=32), block = 256
__global__ void transpose_kernel(const float* __restrict__ x) {
    __shared__ float t[32][57];
    const int h   = blockIdx.x;
    const int icb = blockIdx.y;
    const int b   = blockIdx.z;
    const int tid = threadIdx.x;
    for (int i = tid; i < 32 * 56; i += 256) {
        int ic_l = i / 56, w = i % 56;
        t[ic_l][w] = x[((size_t)(b * CI + icb * 32 + ic_l) * HH + h) * WW + w];
    }
    __syncthreads();
    for (int i = tid; i < 56 * 32; i += 256) {
        int w = i / 32, ic_l = i % 32;
        g_xpad[((size_t)(b * HP + h + 1) * WP + (w + 1)) * CI + icb * 32 + ic_l] =
            tf32r(t[ic_l][w]);
    }
}

// w_eff[o][tap*128+ic] = krow[o,i,s] + kcol[o,i,r], tf32-rounded
__global__ void weff_kernel(const float* __restrict__ w) {
    int idx = blockIdx.x * blockDim.x + threadIdx.x;
    if (idx >= CO * CI) return;
    int o = idx / CI, i = idx % CI;
    const float* wp = w + (size_t)(o * CI + i) * 9;
    float v[9];
#pragma unroll
    for (int t = 0; t < 9; ++t) v[t] = wp[t];
    float krow[3], kcol[3];
#pragma unroll
    for (int j = 0; j < 3; ++j) {
        krow[j] = v[j * 3 + 0] + v[j * 3 + 1] + v[j * 3 + 2];
        kcol[j] = v[0 + j] + v[3 + j] + v[6 + j];
    }
#pragma unroll
    for (int r = 0; r < 3; ++r)
#pragma unroll
        for (int s = 0; s < 3; ++s)
            g_weff[(size_t)o * KTOT + (r * 3 + s) * 128 + i] = tf32r(krow[s] + kcol[r]);
}

// ---------------------------------------------------------------------------
// Main mma.sync tf32 implicit-GEMM conv
// grid = (784 m-tiles, 2 n-tiles), block = 256 (8 warps, each 64x32)
// ---------------------------------------------------------------------------
__global__ __launch_bounds__(256)
void conv_mma_kernel(const float* __restrict__ bias, float* __restrict__ y) {
    extern __shared__ float sm[];

    const int tid  = threadIdx.x;
    const int lane = tid & 31;
    const int wid  = tid >> 5;
    const int m0   = blockIdx.x * 128;
    const int n0   = blockIdx.y * 128;

    // --- staging identity ---
    const int rloc = tid & 127;                 // row within 128-row tile
    const int half = tid >> 7;                  // which 16-float half of the 32-float k-chunk
    {
        const int m  = m0 + rloc;
        const int b  = m / HW;
        const int hw = m % HW;
        const int h  = hw / WW;
        const int w  = hw % WW;
        // base ptr for tap (0,0), icq 0
        // stored in registers via locals below
        (void)b; (void)h; (void)w;
    }
    const int m_g  = m0 + rloc;
    const int b_s  = m_g / HW;
    const int hw_s = m_g % HW;
    const float* aptr0 = g_xpad + ((size_t)(b_s * HP + hw_s / WW) * WP + (hw_s % WW)) * CI + half * 16;
    const float* bptr0 = g_weff + (size_t)(n0 + rloc) * KTOT + half * 16;

    if (tid < 128) sm[OFF_BIAS + tid] = bias[n0 + tid];

    // --- warp compute identity ---
    const int m0w  = (wid & 1) * 64;
    const int n0w  = (wid >> 1) * 32;
    const int qrow = lane >> 2;
    const int qcol = lane & 3;

    float acc[4][4][4];
#pragma unroll
    for (int mt = 0; mt < 4; ++mt)
#pragma unroll
        for (int nt = 0; nt < 4; ++nt)
#pragma unroll
            for (int e = 0; e < 4; ++e) acc[mt][nt][e] = 0.f;

    float4 ra[4], rb[4];

    // prologue: load chunk 0 and stage into buffer 0
    {
        const float* ap = aptr0;                       // tap 0 -> (r,s)=(0,0), icq 0
        const float* bp = bptr0;
#pragma unroll
        for (int j = 0; j < 4; ++j) ra[j] = ((const float4*)ap)[j];
#pragma unroll
        for (int j = 0; j < 4; ++j) rb[j] = ((const float4*)bp)[j];
#pragma unroll
        for (int j = 0; j < 4; ++j) {
            const int kl = half * 16 + j * 4;
            sm[OFF_A0 + (kl + 0) * S_STRIDE + rloc] = ra[j].x;
            sm[OFF_A0 + (kl + 1) * S_STRIDE + rloc] = ra[j].y;
            sm[OFF_A0 + (kl + 2) * S_STRIDE + rloc] = ra[j].z;
            sm[OFF_A0 + (kl + 3) * S_STRIDE + rloc] = ra[j].w;
            sm[OFF_B0 + (kl + 0) * S_STRIDE + rloc] = rb[j].x;
            sm[OFF_B0 + (kl + 1) * S_STRIDE + rloc] = rb[j].y;
            sm[OFF_B0 + (kl + 2) * S_STRIDE + rloc] = rb[j].z;
            sm[OFF_B0 + (kl + 3) * S_STRIDE + rloc] = rb[j].w;
        }
    }

    for (int c = 0; c < NCHUNKS; ++c) {
        __syncthreads();

        // issue next-chunk LDGs early (latency hidden under MMA)
        if (c + 1 < NCHUNKS) {
            const int cn  = c + 1;
            const int tap = cn >> 2;
            const int icq = cn & 3;
            const float* ap = aptr0 + ((size_t)((tap / 3) * WP + (tap % 3))) * CI + icq * 32;
            const float* bp = bptr0 + cn * 32;
#pragma unroll
            for (int j = 0; j < 4; ++j) ra[j] = ((const float4*)ap)[j];
#pragma unroll
            for (int j = 0; j < 4; ++j) rb[j] = ((const float4*)bp)[j];
        }

        // --- compute on buffer c&1 ---
        const int aoff = (c & 1) ? OFF_A1 : OFF_A0;
        const int boff = (c & 1) ? OFF_B1 : OFF_B0;
#pragma unroll
        for (int ks = 0; ks < 4; ++ks) {
            const int kb = ks * 8;
            uint32_t afr[4][4];
#pragma unroll
            for (int mt = 0; mt < 4; ++mt) {
                const int row = m0w + mt * 16 + qrow;
                const int col = kb + qcol;
                afr[mt][0] = __float_as_uint(sm[aoff + (col    ) * S_STRIDE + row    ]);
                afr[mt][1] = __float_as_uint(sm[aoff + (col    ) * S_STRIDE + row + 8]);
                afr[mt][2] = __float_as_uint(sm[aoff + (col + 4) * S_STRIDE + row    ]);
                afr[mt][3] = __float_as_uint(sm[aoff + (col + 4) * S_STRIDE + row + 8]);
            }
            uint32_t bfr[4][2];
#pragma unroll
            for (int nt = 0; nt < 4; ++nt) {
                const int n = n0w + nt * 8 + qrow;
                bfr[nt][0] = __float_as_uint(sm[boff + (kb + qcol    ) * S_STRIDE + n]);
                bfr[nt][1] = __float_as_uint(sm[boff + (kb + qcol + 4) * S_STRIDE + n]);
            }
#pragma unroll
            for (int mt = 0; mt < 4; ++mt)
#pragma unroll
                for (int nt = 0; nt < 4; ++nt)
                    mma_tf32(acc[mt][nt], afr[mt], bfr[nt]);
        }

        // --- stage next chunk into the other buffer ---
        if (c + 1 < NCHUNKS) {
            const int aoff2 = (c & 1) ? OFF_A0 : OFF_A1;
            const int boff2 = (c & 1) ? OFF_B0 : OFF_B1;
#pragma unroll
            for (int j = 0; j < 4; ++j) {
                const int kl = half * 16 + j * 4;
                sm[aoff2 + (kl + 0) * S_STRIDE + rloc] = ra[j].x;
                sm[aoff2 + (kl + 1) * S_STRIDE + rloc] = ra[j].y;
                sm[aoff2 + (kl + 2) * S_STRIDE + rloc] = ra[j].z;
                sm[aoff2 + (kl + 3) * S_STRIDE + rloc] = ra[j].w;
                sm[boff2 + (kl + 0) * S_STRIDE + rloc] = rb[j].x;
                sm[boff2 + (kl + 1) * S_STRIDE + rloc] = rb[j].y;
                sm[boff2 + (kl + 2) * S_STRIDE + rloc] = rb[j].z;
                sm[boff2 + (kl + 3) * S_STRIDE + rloc] = rb[j].w;
            }
        }
    }

    // --- epilogue: scatter accumulators to NCHW output + bias ---
    const float* sbias = sm + OFF_BIAS;
#pragma unroll
    for (int mt = 0; mt < 4; ++mt) {
#pragma unroll
        for (int rr = 0; rr < 2; ++rr) {
            const int mg = m0 + m0w + mt * 16 + qrow + rr * 8;
            const int b  = mg / HW;
            const int hw = mg % HW;
            float* yb = y + (size_t)b * CO * HW + hw;
#pragma unroll
            for (int nt = 0; nt < 4; ++nt) {
                const int ocl = n0w + nt * 8 + 2 * qcol;
                const int oc  = n0 + ocl;
                yb[(size_t)(oc    ) * HW] = acc[mt][nt][rr * 2 + 0] + sbias[ocl];
                yb[(size_t)(oc + 1) * HW] = acc[mt][nt][rr * 2 + 1] + sbias[ocl + 1];
            }
        }
    }
}

// ---------------------------------------------------------------------------
extern "C" void kernel_launch(void* const* d_in, const int* in_sizes, int n_in,
                              void* d_out, int out_size) {
    const float* x    = (const float*)d_in[0];
    const float* w    = (const float*)d_in[1];
    const float* bias = (const float*)d_in[2];
    float* y = (float*)d_out;

    zero_xpad_kernel<<<2048, 256>>>();
    transpose_kernel<<<dim3(HH, CI / 32, BATCH), 256>>>(x);
    weff_kernel<<<(CO * CI + 255) / 256, 256>>>(w);

    cudaFuncSetAttribute(conv_mma_kernel,
                         cudaFuncAttributeMaxDynamicSharedMemorySize, SMEM_TOTAL);
    dim3 grid(BATCH * HW / 128, CO / 128);
    conv_mma_kernel<<<grid, 256, SMEM_TOTAL>>>(bias, y);
}

// round 10
// speedup vs baseline: 3.3255x; 1.2274x over previous
#include <cuda_runtime.h>
#include <cstdint>

#define BATCH 32
#define CI    128
#define CO    256
#define HH    56
#define WW    56
#define HP    58
#define WP    58
#define KTOT  1152          // CI * 9
#define NCHUNKS 36          // KTOT / 32
#define HW    (HH * WW)     // 3136

#define STAGES      3
#define STAGE_BYTES 32768       // A 16KB + B 16KB
#define OFF_B_STAGE 16384
#define OFF_BIAS    (STAGES * STAGE_BYTES)          // byte offset of bias
#define SMEM_TOTAL  (STAGES * STAGE_BYTES + 512)

__device__ float g_xpad[BATCH * HP * WP * CI];   // NHWC, zero halo, tf32-rounded
__device__ float g_weff[CO * KTOT];              // [oc][tap*128+ic], tf32-rounded

__device__ __forceinline__ uint32_t smem_u32(const void* p) {
    uint32_t a;
    asm("{ .reg .u64 t; cvta.to.shared.u64 t, %1; cvt.u32.u64 %0, t; }" : "=r"(a) : "l"(p));
    return a;
}
__device__ __forceinline__ float tf32r(float v) {
    uint32_t r;
    asm("cvt.rna.tf32.f32 %0, %1;" : "=r"(r) : "f"(v));
    return __uint_as_float(r);
}
__device__ __forceinline__ void mma_tf32(float* d, const uint32_t* a, uint32_t b0, uint32_t b1) {
    asm volatile(
        "mma.sync.aligned.m16n8k8.row.col.f32.tf32.tf32.f32 "
        "{%0,%1,%2,%3}, {%4,%5,%6,%7}, {%8,%9}, {%0,%1,%2,%3};"
        : "+f"(d[0]), "+f"(d[1]), "+f"(d[2]), "+f"(d[3])
        : "r"(a[0]), "r"(a[1]), "r"(a[2]), "r"(a[3]), "r"(b0), "r"(b1));
}
__device__ __forceinline__ void ldsm4(uint32_t* r, uint32_t addr) {
    asm volatile("ldmatrix.sync.aligned.m8n8.x4.shared.b16 {%0,%1,%2,%3}, [%4];"
        : "=r"(r[0]), "=r"(r[1]), "=r"(r[2]), "=r"(r[3]) : "r"(addr));
}
__device__ __forceinline__ void cp16(uint32_t saddr, const float* g) {
    asm volatile("cp.async.cg.shared.global [%0], [%1], 16;"
        :: "r"(saddr), "l"(__cvta_generic_to_global(g)) : "memory");
}
#define CP_COMMIT() asm volatile("cp.async.commit_group;" ::: "memory")
#define CP_WAIT1()  asm volatile("cp.async.wait_group 1;" ::: "memory")

// ---------------------------------------------------------------------------
// Prep kernels
// ---------------------------------------------------------------------------
__global__ void zero_xpad_kernel() {
    const int n4 = BATCH * HP * WP * CI / 4;
    float4 z = make_float4(0.f, 0.f, 0.f, 0.f);
    for (int i = blockIdx.x * blockDim.x + threadIdx.x; i < n4; i += gridDim.x * blockDim.x)
        ((float4*)g_xpad)[i] = z;
}

__global__ void transpose_kernel(const float* __restrict__ x) {
    __shared__ float t[32][57];
    const int h = blockIdx.x, icb = blockIdx.y, b = blockIdx.z, tid = threadIdx.x;
    for (int i = tid; i < 32 * 56; i += 256) {
        int ic_l = i / 56, w = i % 56;
        t[ic_l][w] = x[((size_t)(b * CI + icb * 32 + ic_l) * HH + h) * WW + w];
    }
    __syncthreads();
    for (int i = tid; i < 56 * 32; i += 256) {
        int w = i / 32, ic_l = i % 32;
        g_xpad[((size_t)(b * HP + h + 1) * WP + (w + 1)) * CI + icb * 32 + ic_l] =
            tf32r(t[ic_l][w]);
    }
}

__global__ void weff_kernel(const float* __restrict__ w) {
    int idx = blockIdx.x * blockDim.x + threadIdx.x;
    if (idx >= CO * CI) return;
    int o = idx / CI, i = idx % CI;
    const float* wp = w + (size_t)(o * CI + i) * 9;
    float v[9];
#pragma unroll
    for (int t = 0; t < 9; ++t) v[t] = wp[t];
    float krow[3], kcol[3];
#pragma unroll
    for (int j = 0; j < 3; ++j) {
        krow[j] = v[j * 3 + 0] + v[j * 3 + 1] + v[j * 3 + 2];
        kcol[j] = v[0 + j] + v[3 + j] + v[6 + j];
    }
#pragma unroll
    for (int r = 0; r < 3; ++r)
#pragma unroll
        for (int s = 0; s < 3; ++s)
            g_weff[(size_t)o * KTOT + (r * 3 + s) * 128 + i] = tf32r(krow[s] + kcol[r]);
}

// ---------------------------------------------------------------------------
// Main kernel: cp.async 3-stage + ldmatrix + swizzled smem
// grid = (784, 2), block = 256 (8 warps, each 64x32 of the 128x128 CTA tile)
// Smem tile: [row][8 x 16B segments], segment s stored at s ^ (row & 7)
// ---------------------------------------------------------------------------
__global__ __launch_bounds__(256, 2)
void conv_mma_kernel(const float* __restrict__ bias, float* __restrict__ y) {
    extern __shared__ char smem[];
    const uint32_t sb = smem_u32(smem);

    const int tid  = threadIdx.x;
    const int lane = tid & 31;
    const int wid  = tid >> 5;
    const int m0   = blockIdx.x * 128;
    const int n0   = blockIdx.y * 128;

    // ---- staging identity: thread covers row rloc, 4 segments starting at 4*half ----
    const int rloc = tid & 127;
    const int half = tid >> 7;
    const int m_g  = m0 + rloc;
    const int b_s  = m_g / HW;
    const int hw_s = m_g % HW;
    const float* aSrc0 = g_xpad + ((size_t)(b_s * HP + hw_s / WW) * WP + (hw_s % WW)) * CI + half * 16;
    const float* bSrc0 = g_weff + (size_t)(n0 + rloc) * KTOT + half * 16;
    const uint32_t rowOff = (uint32_t)rloc * 128;
    const int rp = rloc & 7;

    if (tid < 128) ((float*)(smem + OFF_BIAS))[tid] = bias[n0 + tid];

    // ---- ldmatrix lane geometry ----
    const int t   = lane >> 3;      // tile index within x4
    const int rin = lane & 7;
    // A: tiles {(+0,seg0),(+8,seg0),(+0,seg1),(+8,seg1)}
    const int m0w = (wid & 1) * 64;
    const int n0w = (wid >> 1) * 32;
    const int thalfA = t >> 1;      // A seg offset
    uint32_t offA[4]; int permA[4];
#pragma unroll
    for (int mt = 0; mt < 4; ++mt) {
        int row = m0w + mt * 16 + (t & 1) * 8 + rin;
        offA[mt] = (uint32_t)row * 128;
        permA[mt] = row & 7;
    }
    // B: tiles {(nt0,seg0),(nt0,seg1),(nt1,seg0),(nt1,seg1)}
    const int segBoff = t & 1;
    uint32_t offB[2]; int permB[2];
#pragma unroll
    for (int p = 0; p < 2; ++p) {
        int row = n0w + p * 16 + (t >> 1) * 8 + rin;
        offB[p] = (uint32_t)row * 128 + OFF_B_STAGE;
        permB[p] = row & 7;
    }

    float acc[4][4][4];
#pragma unroll
    for (int mt = 0; mt < 4; ++mt)
#pragma unroll
        for (int nt = 0; nt < 4; ++nt)
#pragma unroll
            for (int e = 0; e < 4; ++e) acc[mt][nt][e] = 0.f;

    // ---- staging helper ----
    auto stage = [&](int c) {
        const int st  = c % STAGES;
        const int tap = c >> 2;
        const int icq = c & 3;
        const float* ap = aSrc0 + ((size_t)((tap / 3) * WP + (tap % 3))) * CI + icq * 32;
        const float* bp = bSrc0 + c * 32;
        const uint32_t sA = sb + st * STAGE_BYTES + rowOff;
        const uint32_t sB = sA + OFF_B_STAGE;
#pragma unroll
        for (int j = 0; j < 4; ++j) {
            const int s = 4 * half + j;
            const uint32_t ps = (uint32_t)((s ^ rp) << 4);
            cp16(sA + ps, ap + j * 4);
            cp16(sB + ps, bp + j * 4);
        }
    };

    // ---- prologue: stages for chunks 0, 1 ----
    stage(0); CP_COMMIT();
    stage(1); CP_COMMIT();

    for (int c = 0; c < NCHUNKS; ++c) {
        CP_WAIT1();
        __syncthreads();

        if (c + 2 < NCHUNKS) stage(c + 2);
        CP_COMMIT();

        const uint32_t stBase = sb + (c % STAGES) * STAGE_BYTES;
#pragma unroll
        for (int ks = 0; ks < 4; ++ks) {
            uint32_t af[16], bf[8];
#pragma unroll
            for (int mt = 0; mt < 4; ++mt)
                ldsm4(&af[mt * 4],
                      stBase + offA[mt] + (uint32_t)(((2 * ks + thalfA) ^ permA[mt]) << 4));
#pragma unroll
            for (int p = 0; p < 2; ++p)
                ldsm4(&bf[p * 4],
                      stBase + offB[p] + (uint32_t)(((2 * ks + segBoff) ^ permB[p]) << 4));
#pragma unroll
            for (int mt = 0; mt < 4; ++mt)
#pragma unroll
                for (int nt = 0; nt < 4; ++nt)
                    mma_tf32(acc[mt][nt], &af[mt * 4],
                             bf[(nt >> 1) * 4 + (nt & 1) * 2],
                             bf[(nt >> 1) * 4 + (nt & 1) * 2 + 1]);
        }
    }

    // ---- epilogue: scatter to NCHW + bias ----
    const int qrow = lane >> 2;
    const int qcol = lane & 3;
    const float* sbias = (const float*)(smem + OFF_BIAS);
#pragma unroll
    for (int mt = 0; mt < 4; ++mt) {
#pragma unroll
        for (int rr = 0; rr < 2; ++rr) {
            const int mg = m0 + m0w + mt * 16 + qrow + rr * 8;
            const int b  = mg / HW;
            const int hw = mg % HW;
            float* yb = y + (size_t)b * CO * HW + hw;
#pragma unroll
            for (int nt = 0; nt < 4; ++nt) {
                const int ocl = n0w + nt * 8 + 2 * qcol;
                const int oc  = n0 + ocl;
                yb[(size_t)(oc    ) * HW] = acc[mt][nt][rr * 2 + 0] + sbias[ocl];
                yb[(size_t)(oc + 1) * HW] = acc[mt][nt][rr * 2 + 1] + sbias[ocl + 1];
            }
        }
    }
}

// ---------------------------------------------------------------------------
extern "C" void kernel_launch(void* const* d_in, const int* in_sizes, int n_in,
                              void* d_out, int out_size) {
    const float* x    = (const float*)d_in[0];
    const float* w    = (const float*)d_in[1];
    const float* bias = (const float*)d_in[2];
    float* y = (float*)d_out;

    zero_xpad_kernel<<<2048, 256>>>();
    transpose_kernel<<<dim3(HH, CI / 32, BATCH), 256>>>(x);
    weff_kernel<<<(CO * CI + 255) / 256, 256>>>(w);

    cudaFuncSetAttribute(conv_mma_kernel,
                         cudaFuncAttributeMaxDynamicSharedMemorySize, SMEM_TOTAL);
    dim3 grid(BATCH * HW / 128, CO / 128);
    conv_mma_kernel<<<grid, 256, SMEM_TOTAL>>>(bias, y);
}

// round 12
// speedup vs baseline: 4.3274x; 1.3013x over previous
#include <cuda_runtime.h>
#include <cstdint>

#define BATCH 32
#define CI    128
#define CO    256
#define HH    56
#define WW    56
#define HP    58
#define WP    58
#define KTOT2 768           // 6 groups x 128 ic
#define NCHUNKS 24          // KTOT2 / 32
#define HW    (HH * WW)     // 3136

#define STAGES      3
#define STAGE_BYTES 32768       // A 16KB + B 16KB
#define OFF_B_STAGE 16384
#define OFF_BIAS    (STAGES * STAGE_BYTES)
#define SMEM_TOTAL  (STAGES * STAGE_BYTES + 512)

__device__ float g_xpad[BATCH * HP * WP * CI];   // NHWC, zero halo, full fp32
__device__ float g_vsum[BATCH * HH * WP * CI];   // vertical 3-sum, tf32-rounded
__device__ float g_hsum[BATCH * HP * WW * CI];   // horizontal 3-sum, tf32-rounded
__device__ float g_weff[CO * KTOT2];             // [oc][g*128+ic] = krow|kcol, tf32

__device__ __forceinline__ uint32_t smem_u32(const void* p) {
    uint32_t a;
    asm("{ .reg .u64 t; cvta.to.shared.u64 t, %1; cvt.u32.u64 %0, t; }" : "=r"(a) : "l"(p));
    return a;
}
__device__ __forceinline__ float tf32r(float v) {
    uint32_t r;
    asm("cvt.rna.tf32.f32 %0, %1;" : "=r"(r) : "f"(v));
    return __uint_as_float(r);
}
__device__ __forceinline__ void mma_tf32(float* d, const uint32_t* a, uint32_t b0, uint32_t b1) {
    asm volatile(
        "mma.sync.aligned.m16n8k8.row.col.f32.tf32.tf32.f32 "
        "{%0,%1,%2,%3}, {%4,%5,%6,%7}, {%8,%9}, {%0,%1,%2,%3};"
        : "+f"(d[0]), "+f"(d[1]), "+f"(d[2]), "+f"(d[3])
        : "r"(a[0]), "r"(a[1]), "r"(a[2]), "r"(a[3]), "r"(b0), "r"(b1));
}
__device__ __forceinline__ void ldsm4(uint32_t* r, uint32_t addr) {
    asm volatile("ldmatrix.sync.aligned.m8n8.x4.shared.b16 {%0,%1,%2,%3}, [%4];"
        : "=r"(r[0]), "=r"(r[1]), "=r"(r[2]), "=r"(r[3]) : "r"(addr));
}
__device__ __forceinline__ void cp16(uint32_t saddr, const float* g) {
    asm volatile("cp.async.cg.shared.global [%0], [%1], 16;"
        :: "r"(saddr), "l"(__cvta_generic_to_global(g)) : "memory");
}
#define CP_COMMIT() asm volatile("cp.async.commit_group;" ::: "memory")
#define CP_WAIT1()  asm volatile("cp.async.wait_group 1;" ::: "memory")

// ---------------------------------------------------------------------------
// Prep kernels
// ---------------------------------------------------------------------------
__global__ void zero_xpad_kernel() {
    const int n4 = BATCH * HP * WP * CI / 4;
    float4 z = make_float4(0.f, 0.f, 0.f, 0.f);
    for (int i = blockIdx.x * blockDim.x + threadIdx.x; i < n4; i += gridDim.x * blockDim.x)
        ((float4*)g_xpad)[i] = z;
}

// NCHW -> padded NHWC (full fp32; rounding happens after the 3-sums)
__global__ void transpose_kernel(const float* __restrict__ x) {
    __shared__ float t[32][57];
    const int h = blockIdx.x, icb = blockIdx.y, b = blockIdx.z, tid = threadIdx.x;
    for (int i = tid; i < 32 * 56; i += 256) {
        int ic_l = i / 56, w = i % 56;
        t[ic_l][w] = x[((size_t)(b * CI + icb * 32 + ic_l) * HH + h) * WW + w];
    }
    __syncthreads();
    for (int i = tid; i < 56 * 32; i += 256) {
        int w = i / 32, ic_l = i % 32;
        g_xpad[((size_t)(b * HP + h + 1) * WP + (w + 1)) * CI + icb * 32 + ic_l] = t[ic_l][w];
    }
}

// vsum[b][h][wp][ic] = sum_{d=0..2} xpad[b][h+d][wp][ic], tf32-rounded
__global__ void vsum_kernel() {
    const int h = blockIdx.x, b = blockIdx.y;
    const float4* r0 = (const float4*)&g_xpad[((size_t)(b * HP + h    ) * WP) * CI];
    const float4* r1 = (const float4*)&g_xpad[((size_t)(b * HP + h + 1) * WP) * CI];
    const float4* r2 = (const float4*)&g_xpad[((size_t)(b * HP + h + 2) * WP) * CI];
    float4* dst = (float4*)&g_vsum[((size_t)(b * HH + h) * WP) * CI];
    for (int i = threadIdx.x; i < WP * CI / 4; i += blockDim.x) {
        float4 a = r0[i], c = r1[i], e = r2[i];
        float4 o;
        o.x = tf32r(a.x + c.x + e.x);
        o.y = tf32r(a.y + c.y + e.y);
        o.z = tf32r(a.z + c.z + e.z);
        o.w = tf32r(a.w + c.w + e.w);
        dst[i] = o;
    }
}

// hsum[b][hp][w][ic] = sum_{d=0..2} xpad[b][hp][w+d][ic], tf32-rounded
__global__ void hsum_kernel() {
    const int hp = blockIdx.x, b = blockIdx.y;
    const float4* row = (const float4*)&g_xpad[((size_t)(b * HP + hp) * WP) * CI];
    float4* dst = (float4*)&g_hsum[((size_t)(b * HP + hp) * WW) * CI];
    const int C4 = CI / 4;
    for (int i = threadIdx.x; i < WW * C4; i += blockDim.x) {
        int w = i / C4, q = i % C4;
        float4 a = row[(w    ) * C4 + q];
        float4 c = row[(w + 1) * C4 + q];
        float4 e = row[(w + 2) * C4 + q];
        float4 o;
        o.x = tf32r(a.x + c.x + e.x);
        o.y = tf32r(a.y + c.y + e.y);
        o.z = tf32r(a.z + c.z + e.z);
        o.w = tf32r(a.w + c.w + e.w);
        dst[i] = o;
    }
}

// weff[o][g*128+i]:
//   g in 0..2  pairs with vsum shifted by s=g  -> krow[o,i,s=g] = sum over row g's columns
//   g in 3..5  pairs with hsum shifted by r=g-3 -> kcol[o,i,r=g-3] = sum over column (g-3)'s rows
__global__ void weff_kernel(const float* __restrict__ w) {
    int idx = blockIdx.x * blockDim.x + threadIdx.x;
    if (idx >= CO * CI) return;
    int o = idx / CI, i = idx % CI;
    const float* wp = w + (size_t)(o * CI + i) * 9;
    float v[9];
#pragma unroll
    for (int t = 0; t < 9; ++t) v[t] = wp[t];
#pragma unroll
    for (int j = 0; j < 3; ++j) {
        // krow[j] (reference: weight.sum(axis=3) indexed at j): row j summed over columns
        float krow = v[j * 3 + 0] + v[j * 3 + 1] + v[j * 3 + 2];
        // kcol[j] (reference: weight.sum(axis=2) indexed at j): column j summed over rows
        float kcol = v[0 * 3 + j] + v[1 * 3 + j] + v[2 * 3 + j];
        g_weff[(size_t)o * KTOT2 + (j    ) * 128 + i] = tf32r(krow);   // vsum partner
        g_weff[(size_t)o * KTOT2 + (j + 3) * 128 + i] = tf32r(kcol);   // hsum partner
    }
}

// ---------------------------------------------------------------------------
// Main kernel: cp.async 3-stage + ldmatrix + swizzled smem, K = 768
// grid = (784, 2), block = 256 (8 warps, each 64x32 of the 128x128 CTA tile)
// ---------------------------------------------------------------------------
__global__ __launch_bounds__(256, 2)
void conv_mma_kernel(const float* __restrict__ bias, float* __restrict__ y) {
    extern __shared__ char smem[];
    const uint32_t sb = smem_u32(smem);

    const int tid  = threadIdx.x;
    const int lane = tid & 31;
    const int wid  = tid >> 5;
    const int m0   = blockIdx.x * 128;
    const int n0   = blockIdx.y * 128;

    // ---- staging identity ----
    const int rloc = tid & 127;
    const int half = tid >> 7;
    const int m_g  = m0 + rloc;
    const int b_s  = m_g / HW;
    const int hw_s = m_g % HW;
    const int h_s  = hw_s / WW;
    const int w_s  = hw_s % WW;
    const float* vbase = g_vsum + (((size_t)(b_s * HH + h_s) * WP) + w_s) * CI + half * 16;
    const float* hbase = g_hsum + (((size_t)(b_s * HP + h_s) * WW) + w_s) * CI + half * 16;
    const float* bSrc0 = g_weff + (size_t)(n0 + rloc) * KTOT2 + half * 16;
    const uint32_t rowOff = (uint32_t)rloc * 128;
    const int rp = rloc & 7;

    if (tid < 128) ((float*)(smem + OFF_BIAS))[tid] = bias[n0 + tid];

    // ---- ldmatrix lane geometry ----
    const int t   = lane >> 3;
    const int rin = lane & 7;
    const int m0w = (wid & 1) * 64;
    const int n0w = (wid >> 1) * 32;
    const int thalfA = t >> 1;
    uint32_t offA[4]; int permA[4];
#pragma unroll
    for (int mt = 0; mt < 4; ++mt) {
        int row = m0w + mt * 16 + (t & 1) * 8 + rin;
        offA[mt] = (uint32_t)row * 128;
        permA[mt] = row & 7;
    }
    const int segBoff = t & 1;
    uint32_t offB[2]; int permB[2];
#pragma unroll
    for (int p = 0; p < 2; ++p) {
        int row = n0w + p * 16 + (t >> 1) * 8 + rin;
        offB[p] = (uint32_t)row * 128 + OFF_B_STAGE;
        permB[p] = row & 7;
    }

    float acc[4][4][4];
#pragma unroll
    for (int mt = 0; mt < 4; ++mt)
#pragma unroll
        for (int nt = 0; nt < 4; ++nt)
#pragma unroll
            for (int e = 0; e < 4; ++e) acc[mt][nt][e] = 0.f;

    // ---- staging helper: group g = c>>2 selects vsum (g<3) or hsum (g>=3) ----
    auto stage = [&](int c) {
        const int st  = c % STAGES;
        const int g   = c >> 2;
        const int icq = c & 3;
        const float* ap = (g < 3)
            ? vbase + (size_t)g * CI + icq * 32
            : hbase + (size_t)(g - 3) * WW * CI + icq * 32;
        const float* bp = bSrc0 + c * 32;
        const uint32_t sA = sb + st * STAGE_BYTES + rowOff;
        const uint32_t sB = sA + OFF_B_STAGE;
#pragma unroll
        for (int j = 0; j < 4; ++j) {
            const int s = 4 * half + j;
            const uint32_t ps = (uint32_t)((s ^ rp) << 4);
            cp16(sA + ps, ap + j * 4);
            cp16(sB + ps, bp + j * 4);
        }
    };

    stage(0); CP_COMMIT();
    stage(1); CP_COMMIT();

    for (int c = 0; c < NCHUNKS; ++c) {
        CP_WAIT1();
        __syncthreads();

        if (c + 2 < NCHUNKS) stage(c + 2);
        CP_COMMIT();

        const uint32_t stBase = sb + (c % STAGES) * STAGE_BYTES;
#pragma unroll
        for (int ks = 0; ks < 4; ++ks) {
            uint32_t af[16], bf[8];
#pragma unroll
            for (int mt = 0; mt < 4; ++mt)
                ldsm4(&af[mt * 4],
                      stBase + offA[mt] + (uint32_t)(((2 * ks + thalfA) ^ permA[mt]) << 4));
#pragma unroll
            for (int p = 0; p < 2; ++p)
                ldsm4(&bf[p * 4],
                      stBase + offB[p] + (uint32_t)(((2 * ks + segBoff) ^ permB[p]) << 4));
#pragma unroll
            for (int mt = 0; mt < 4; ++mt)
#pragma unroll
                for (int nt = 0; nt < 4; ++nt)
                    mma_tf32(acc[mt][nt], &af[mt * 4],
                             bf[(nt >> 1) * 4 + (nt & 1) * 2],
                             bf[(nt >> 1) * 4 + (nt & 1) * 2 + 1]);
        }
    }

    // ---- epilogue: scatter to NCHW + bias ----
    const int qrow = lane >> 2;
    const int qcol = lane & 3;
    const float* sbias = (const float*)(smem + OFF_BIAS);
#pragma unroll
    for (int mt = 0; mt < 4; ++mt) {
#pragma unroll
        for (int rr = 0; rr < 2; ++rr) {
            const int mg = m0 + m0w + mt * 16 + qrow + rr * 8;
            const int b  = mg / HW;
            const int hw = mg % HW;
            float* yb = y + (size_t)b * CO * HW + hw;
#pragma unroll
            for (int nt = 0; nt < 4; ++nt) {
                const int ocl = n0w + nt * 8 + 2 * qcol;
                const int oc  = n0 + ocl;
                yb[(size_t)(oc    ) * HW] = acc[mt][nt][rr * 2 + 0] + sbias[ocl];
                yb[(size_t)(oc + 1) * HW] = acc[mt][nt][rr * 2 + 1] + sbias[ocl + 1];
            }
        }
    }
}

// ---------------------------------------------------------------------------
extern "C" void kernel_launch(void* const* d_in, const int* in_sizes, int n_in,
                              void* d_out, int out_size) {
    const float* x    = (const float*)d_in[0];
    const float* w    = (const float*)d_in[1];
    const float* bias = (const float*)d_in[2];
    float* y = (float*)d_out;

    zero_xpad_kernel<<<2048, 256>>>();
    transpose_kernel<<<dim3(HH, CI / 32, BATCH), 256>>>(x);
    vsum_kernel<<<dim3(HH, BATCH), 256>>>();
    hsum_kernel<<<dim3(HP, BATCH), 256>>>();
    weff_kernel<<<(CO * CI + 255) / 256, 256>>>(w);

    cudaFuncSetAttribute(conv_mma_kernel,
                         cudaFuncAttributeMaxDynamicSharedMemorySize, SMEM_TOTAL);
    dim3 grid(BATCH * HW / 128, CO / 128);
    conv_mma_kernel<<<grid, 256, SMEM_TOTAL>>>(bias, y);
}